// round 16
// baseline (speedup 1.0000x reference)
#include <cuda_runtime.h>
#include <cuda_fp16.h>

#define NN 10000
#define FI 256
#define FO 64
#define BM 128
#define BN 64
#define NSPLIT 11
#define RT 79          // ceil(NN/BM)
#define NT 157         // ceil(NN/BN) == bitmask j-tiles
#define NRB 313        // ceil(NN/32) row-blocks for compress
#define LOG2E 1.4426950408889634f

// ---------------- device scratch (no allocation allowed) ----------------
__device__ __half g_WhT[(size_t)FO * NN];          // n-major fp16 Wh^T
__device__ __half2 g_e1p[NN];                      // (exp2(f1'), exp2(0.2 f1'))
__device__ __half g_e2h[NN];                       // exp2(f2')
__device__ __half g_e2l[NN];                       // exp2(0.2 f2')
__device__ unsigned long long g_bm[(size_t)NT * NN];  // permuted adj bitmask, 12.6MB
__device__ float g_pacc[(size_t)NSPLIT * RT * BM * FO];
__device__ float g_pden[NSPLIT * RT * BM];

// ---------------- gat smem layout (bytes) ----------------
#define PSTB 144                      // B row stride: 128B + 16B pad (ldmatrix)
#define SM_LUT 0                      // 16 x uint2
#define SM_E2H 640                    // 32 half2
#define SM_E2L 768                    // 32 half2
#define SM_B   1024                   // 64 * 144
#define SM_TOTAL (SM_B + FO * PSTB)   // 10240

// ---------------- PTX helpers ----------------
__device__ __forceinline__ unsigned s2u(const void* p) {
    unsigned a;
    asm("{ .reg .u64 t; cvta.to.shared.u64 t, %1; cvt.u32.u64 %0, t; }"
        : "=r"(a) : "l"(p));
    return a;
}
__device__ __forceinline__ void ldsm4(unsigned* r, unsigned addr) {
    asm volatile("ldmatrix.sync.aligned.m8n8.x4.shared.b16 {%0,%1,%2,%3}, [%4];"
                 : "=r"(r[0]), "=r"(r[1]), "=r"(r[2]), "=r"(r[3]) : "r"(addr));
}
__device__ __forceinline__ void hmma(float* c, const unsigned* a, const unsigned* b) {
    asm volatile(
        "mma.sync.aligned.m16n8k16.row.col.f32.f16.f16.f32 "
        "{%0,%1,%2,%3}, {%4,%5,%6,%7}, {%8,%9}, {%0,%1,%2,%3};"
        : "+f"(c[0]), "+f"(c[1]), "+f"(c[2]), "+f"(c[3])
        : "r"(a[0]), "r"(a[1]), "r"(a[2]), "r"(a[3]), "r"(b[0]), "r"(b[1]));
}
__device__ __forceinline__ unsigned long long dswap(unsigned long long x,
                                                    unsigned long long m, int s) {
    unsigned long long t = ((x >> s) ^ x) & m;
    return x ^ t ^ (t << s);
}

// -------- Kernel 1: Wh = h @ W -> fp16 Wh^T + fused f1/f2 exp2 tables -----
__global__ __launch_bounds__(256) void wh_kernel(const float* __restrict__ h,
                                                 const float* __restrict__ W,
                                                 const float* __restrict__ a) {
    __shared__ float sh[16 * FI];
    __shared__ float sred[16][2][2];
    int row0 = blockIdx.x * 16;
    const float* hp = h + (long long)row0 * FI;
    for (int t = threadIdx.x; t < 16 * FI; t += 256) sh[t] = hp[t];
    __syncthreads();
    int c = threadIdx.x & 63;
    int ty = threadIdx.x >> 6;
    float acc[4] = {0.f, 0.f, 0.f, 0.f};
    for (int k = 0; k < FI; ++k) {
        float w = W[k * FO + c];
        acc[0] += sh[(ty * 4 + 0) * FI + k] * w;
        acc[1] += sh[(ty * 4 + 1) * FI + k] * w;
        acc[2] += sh[(ty * 4 + 2) * FI + k] * w;
        acc[3] += sh[(ty * 4 + 3) * FI + k] * w;
    }
    __half hb[4];
    #pragma unroll
    for (int q = 0; q < 4; ++q) hb[q] = __float2half_rn(acc[q]);
    size_t off = (size_t)c * NN + row0 + ty * 4;
    *(uint2*)&g_WhT[off] = *(uint2*)hb;

    float a1 = a[c], a2 = a[FO + c];
    float s1[4], s2[4];
    #pragma unroll
    for (int q = 0; q < 4; ++q) { s1[q] = acc[q] * a1; s2[q] = acc[q] * a2; }
    #pragma unroll
    for (int o = 16; o > 0; o >>= 1)
        #pragma unroll
        for (int q = 0; q < 4; ++q) {
            s1[q] += __shfl_xor_sync(0xffffffffu, s1[q], o);
            s2[q] += __shfl_xor_sync(0xffffffffu, s2[q], o);
        }
    if ((threadIdx.x & 31) == 0) {
        int wp = (threadIdx.x >> 5) & 1;
        #pragma unroll
        for (int q = 0; q < 4; ++q) {
            sred[ty * 4 + q][wp][0] = s1[q];
            sred[ty * 4 + q][wp][1] = s2[q];
        }
    }
    __syncthreads();
    if (threadIdx.x < 16) {
        float f1 = (sred[threadIdx.x][0][0] + sred[threadIdx.x][1][0]) * LOG2E;
        float f2 = (sred[threadIdx.x][0][1] + sred[threadIdx.x][1][1]) * LOG2E;
        int row = row0 + threadIdx.x;
        g_e1p[row] = __floats2half2_rn(exp2f(f1), exp2f(0.2f * f1));
        g_e2h[row] = __float2half_rn(exp2f(f2));
        g_e2l[row] = __float2half_rn(exp2f(0.2f * f2));
    }
}

// -------- Kernel 2: adj -> permuted 1-bit mask (pure DRAM stream) ---------
// Straight bit j (within a 64-col tile) moves to p' = 16q + 4ks + 2hi + lo
// where j = 16ks + 8hi + 2q + lo. Realized by 4 delta-swaps (verified).
__global__ __launch_bounds__(256) void adj_compress(const int* __restrict__ adj) {
    int w = (blockIdx.x * 256 + threadIdx.x) >> 5;
    int lane = threadIdx.x & 31;
    int jt = w / NRB;
    int rb = (w - jt * NRB) * 32;
    if (jt >= NT) return;
    int c0 = jt * 64 + lane;
    int c1 = c0 + 32;
    unsigned my0 = 0, my1 = 0;
    #pragma unroll 8
    for (int it = 0; it < 32; ++it) {
        int row = rb + it;
        bool ok = row < NN;
        int v0 = (ok && c0 < NN) ? adj[(size_t)row * NN + c0] : 0;
        int v1 = (ok && c1 < NN) ? adj[(size_t)row * NN + c1] : 0;
        unsigned b0 = __ballot_sync(0xffffffffu, v0 != 0);
        unsigned b1 = __ballot_sync(0xffffffffu, v1 != 0);
        if (lane == it) { my0 = b0; my1 = b1; }
    }
    unsigned long long x = ((unsigned long long)my1 << 32) | my0;
    x = dswap(x, 0x00000000F0F0F0F0ULL, 28);   // idx bits 5<->2
    x = dswap(x, 0x0000CCCC0000CCCCULL, 14);   // idx bits 4<->1
    x = dswap(x, 0x00F000F000F000F0ULL, 4);    // idx bits 3<->2
    x = dswap(x, 0x0C0C0C0C0C0C0C0CULL, 2);    // idx bits 2<->1
    int row = rb + lane;
    if (row < NN) g_bm[(size_t)jt * NN + row] = x;
}

// profiling anchor: keeps gat_mma in ncu's fixed capture slot
__global__ void prof_pad() {}

// ---- Kernel 3: L2-resident mask + fp16-packed P-gen + LUT + mma.sync ----
__global__ __launch_bounds__(256, 3) void gat_mma() {
    extern __shared__ char smem[];
    const unsigned sb = s2u(smem);
    uint2* slut = (uint2*)(smem + SM_LUT);
    __half2* sE2h = (__half2*)(smem + SM_E2H);
    __half2* sE2l = (__half2*)(smem + SM_E2L);

    const int tid = threadIdx.x, wid = tid >> 5, lane = tid & 31;
    const int q = lane & 3, r0 = lane >> 2;
    const int mt = blockIdx.x, jq = blockIdx.y;
    const int i0 = mt * BM;
    const int m0 = wid * 16;

    // B-stage map
    const int bc = tid >> 2, bseg = tid & 3;

    // B fragment addressing (ldmatrix)
    const unsigned b_addr = sb + SM_B +
        ((lane & 7) + ((lane >> 4) & 1) * 8) * PSTB + ((lane >> 3) & 1) * 16;
    unsigned bd[2];
    bd[0] = bd[1] = (lane < 4) ? 0x3C003C00u : 0u;

    float acc[8][4], accD[4];
    #pragma unroll
    for (int nt = 0; nt < 8; ++nt)
        #pragma unroll
        for (int c = 0; c < 4; ++c) acc[nt][c] = 0.f;
    #pragma unroll
    for (int c = 0; c < 4; ++c) accD[c] = 0.f;

    if (tid < 16)
        slut[tid] = make_uint2(
            ((tid & 1) ? 0xFFFFu : 0u) | ((tid & 2) ? 0xFFFF0000u : 0u),
            ((tid & 4) ? 0xFFFFu : 0u) | ((tid & 8) ? 0xFFFF0000u : 0u));

    const int rowA = i0 + m0 + r0;
    const int rowB = rowA + 8;
    const bool okA = rowA < NN, okB = rowB < NN;
    const __half2 e1A = okA ? g_e1p[rowA] : __float2half2_rn(0.f);
    const __half2 e1B = okB ? g_e1p[rowB] : __float2half2_rn(0.f);
    const __half2 E0h = __half2half2(__low2half(e1A));
    const __half2 E0l = __half2half2(__high2half(e1A));
    const __half2 E1h = __half2half2(__low2half(e1B));
    const __half2 E1l = __half2half2(__high2half(e1B));

    // prologue: masks for the first tile (L2-resident)
    unsigned long long WA = okA ? g_bm[(size_t)jq * NN + rowA] : 0ull;
    unsigned long long WB = okB ? g_bm[(size_t)jq * NN + rowB] : 0ull;

    for (int t = jq; t < NT; t += NSPLIT) {
        const int j0 = t * BN;

        // extract this thread's 16 mask bits, then prefetch next tile's words
        const unsigned RA = (unsigned)(WA >> (16 * q)) & 0xFFFFu;
        const unsigned RB = (unsigned)(WB >> (16 * q)) & 0xFFFFu;
        const int tn = t + NSPLIT;
        if (tn < NT) {
            WA = okA ? g_bm[(size_t)tn * NN + rowA] : 0ull;
            WB = okB ? g_bm[(size_t)tn * NN + rowB] : 0ull;
        }

        __syncthreads();   // previous tile's B/e2 reads complete

        // ---- stage B tile (WhT fp16) + e2 half tables ----
        #pragma unroll
        for (int ch = 0; ch < 2; ++ch) {
            int e0 = bseg * 16 + ch * 8;
            uint4 v = make_uint4(0, 0, 0, 0);
            if (j0 + e0 + 7 < NN)
                v = *(const uint4*)(g_WhT + (size_t)bc * NN + j0 + e0);
            *(uint4*)(smem + SM_B + bc * PSTB + e0 * 2) = v;
        }
        if (tid < 32) {
            int j = j0 + 2 * tid;
            bool okj = j < NN;   // NN even -> j+1 in range too
            sE2h[tid] = okj ? *(const __half2*)&g_e2h[j] : __float2half2_rn(0.f);
            sE2l[tid] = okj ? *(const __half2*)&g_e2l[j] : __float2half2_rn(0.f);
        }
        __syncthreads();

        // ---- per k-step: packed-fp16 A-frags + LUT masks, ldsm B, HMMA ----
        #pragma unroll
        for (int ks = 0; ks < 4; ++ks) {
            unsigned nibA = (RA >> (4 * ks)) & 0xFu;
            unsigned nibB = (RB >> (4 * ks)) & 0xFu;
            uint2 mA = slut[nibA];
            uint2 mB = slut[nibB];
            __half2 eh0 = sE2h[8 * ks + q], eh8 = sE2h[8 * ks + q + 4];
            __half2 el0 = sE2l[8 * ks + q], el8 = sE2l[8 * ks + q + 4];

            __half2 pA0 = __hmax2(__hmul2(E0h, eh0), __hmul2(E0l, el0));
            __half2 pB0 = __hmax2(__hmul2(E1h, eh0), __hmul2(E1l, el0));
            __half2 pA8 = __hmax2(__hmul2(E0h, eh8), __hmul2(E0l, el8));
            __half2 pB8 = __hmax2(__hmul2(E1h, eh8), __hmul2(E1l, el8));

            unsigned af[4];
            af[0] = (*(unsigned*)&pA0) & mA.x;
            af[1] = (*(unsigned*)&pB0) & mB.x;
            af[2] = (*(unsigned*)&pA8) & mA.y;
            af[3] = (*(unsigned*)&pB8) & mB.y;

            unsigned bfr[16];
            #pragma unroll
            for (int g = 0; g < 4; ++g)
                ldsm4(bfr + 4 * g, b_addr + g * 16 * PSTB + ks * 32);
            #pragma unroll
            for (int nt = 0; nt < 8; ++nt)
                hmma(acc[nt], af, bfr + nt * 2);
            hmma(accD, af, bd);
        }
    }

    // ---- epilogue ----
    {
        float* pa = g_pacc + (size_t)(jq * RT + mt) * BM * FO;
        int row = m0 + r0;
        int col = q * 2;
        #pragma unroll
        for (int nt = 0; nt < 8; ++nt) {
            *(float2*)&pa[row * FO + nt * 8 + col] = make_float2(acc[nt][0], acc[nt][1]);
            *(float2*)&pa[(row + 8) * FO + nt * 8 + col] = make_float2(acc[nt][2], acc[nt][3]);
        }
    }
    if (q == 0) {
        float* pd = g_pden + (jq * RT + mt) * BM;
        int row = m0 + r0;
        pd[row] = accD[0];
        pd[row + 8] = accD[2];
    }
}

// ---------------- Kernel 4: combine partials + ELU ----------------
__global__ __launch_bounds__(256) void combine_kernel(float* __restrict__ out) {
    int idx = blockIdx.x * 256 + threadIdx.x;
    if (idx >= NN * FO) return;
    int i = idx >> 6, c = idx & 63;
    int mt = i >> 7, row = i & 127;
    float a = 0.f, d = 0.f;
    #pragma unroll
    for (int q = 0; q < NSPLIT; ++q) {
        a += g_pacc[(size_t)(q * RT + mt) * BM * FO + row * FO + c];
        d += g_pden[(q * RT + mt) * BM + row];
    }
    float v = a / d;
    out[idx] = v > 0.f ? v : expm1f(v);
}

extern "C" void kernel_launch(void* const* d_in, const int* in_sizes, int n_in,
                              void* d_out, int out_size) {
    const float* h   = (const float*)d_in[0];
    const int*   adj = (const int*)d_in[1];
    const float* W   = (const float*)d_in[2];
    const float* a   = (const float*)d_in[3];
    float* out = (float*)d_out;

    wh_kernel<<<NN / 16, 256>>>(h, W, a);
    adj_compress<<<(NT * NRB + 7) / 8, 256>>>(adj);
    prof_pad<<<1, 1>>>();   // keeps gat_mma in ncu's capture slot
    gat_mma<<<dim3(RT, NSPLIT), 256, SM_TOTAL>>>();
    combine_kernel<<<(NN * FO + 255) / 256, 256>>>(out);
}

// round 17
// speedup vs baseline: 1.5727x; 1.5727x over previous
#include <cuda_runtime.h>
#include <cuda_fp16.h>

#define NN 10000
#define FI 256
#define FO 64
#define BM 128
#define BN 64
#define NSPLIT 11
#define RT 79          // ceil(NN/BM)
#define NT 157         // ceil(NN/BN)
#define LOG2E 1.4426950408889634f

// ---------------- device scratch (no allocation allowed) ----------------
__device__ __half g_WhT[(size_t)FO * NN];   // n-major fp16 Wh^T
__device__ __half2 g_e1p[NN];               // (exp2(f1'), exp2(0.2 f1')) fp16
__device__ __half g_e2h[NN];                // exp2(f2')
__device__ __half g_e2l[NN];                // exp2(0.2 f2')
__device__ float g_pacc[(size_t)NSPLIT * RT * BM * FO];
__device__ float g_pden[NSPLIT * RT * BM];

// ---------------- gat smem layout (bytes) ----------------
#define PSTB 144                      // B row stride: 128B + 16B pad (ldmatrix)
#define SM_E2Q 0                      // 16 x uint4 = 256B
#define SM_B   256                    // 64 * 144 = 9216
#define SM_ADJ 9472                   // 128 rows * 256B = 32768
#define SM_TOTAL (SM_ADJ + BM * BN * 4)   // 42240 (x3 CTAs = 124KB/SM)

// ---------------- PTX helpers ----------------
__device__ __forceinline__ unsigned s2u(const void* p) {
    unsigned a;
    asm("{ .reg .u64 t; cvta.to.shared.u64 t, %1; cvt.u32.u64 %0, t; }"
        : "=r"(a) : "l"(p));
    return a;
}
__device__ __forceinline__ void ldsm4(unsigned* r, unsigned addr) {
    asm volatile("ldmatrix.sync.aligned.m8n8.x4.shared.b16 {%0,%1,%2,%3}, [%4];"
                 : "=r"(r[0]), "=r"(r[1]), "=r"(r[2]), "=r"(r[3]) : "r"(addr));
}
__device__ __forceinline__ void hmma(float* c, const unsigned* a, const unsigned* b) {
    asm volatile(
        "mma.sync.aligned.m16n8k16.row.col.f32.f16.f16.f32 "
        "{%0,%1,%2,%3}, {%4,%5,%6,%7}, {%8,%9}, {%0,%1,%2,%3};"
        : "+f"(c[0]), "+f"(c[1]), "+f"(c[2]), "+f"(c[3])
        : "r"(a[0]), "r"(a[1]), "r"(a[2]), "r"(a[3]), "r"(b[0]), "r"(b[1]));
}
__device__ __forceinline__ void cp16(unsigned dst, const void* src, unsigned sz) {
    asm volatile("cp.async.cg.shared.global [%0], [%1], 16, %2;"
                 :: "r"(dst), "l"(src), "r"(sz) : "memory");
}
__device__ __forceinline__ void cp_commit() {
    asm volatile("cp.async.commit_group;" ::: "memory");
}
__device__ __forceinline__ void cp_wait0() {
    asm volatile("cp.async.wait_group 0;" ::: "memory");
}
// mask32 from 2 bits of nib: low16 <- bit0, high16 <- bit1 (PRMT, no LDS)
__device__ __forceinline__ unsigned msk2(unsigned nib) {
    return __byte_perm(0u, 0xFFFFFFFFu,
                       (nib & 1u) * 0x44u + (nib & 2u) * 0x2200u);
}
// guarded half2-bits load from a __half array
__device__ __forceinline__ unsigned ldh2g(const __half* b, int j) {
    if (j + 1 < NN) return *(const unsigned*)(b + j);
    if (j < NN) return (unsigned)*(const unsigned short*)(b + j);
    return 0u;
}

// -------- Kernel 1: Wh = h @ W -> fp16 Wh^T + fused f1/f2 exp2 tables -----
__global__ __launch_bounds__(256) void wh_kernel(const float* __restrict__ h,
                                                 const float* __restrict__ W,
                                                 const float* __restrict__ a) {
    __shared__ float sh[16 * FI];
    __shared__ float sred[16][2][2];
    int row0 = blockIdx.x * 16;
    const float* hp = h + (long long)row0 * FI;
    for (int t = threadIdx.x; t < 16 * FI; t += 256) sh[t] = hp[t];
    __syncthreads();
    int c = threadIdx.x & 63;
    int ty = threadIdx.x >> 6;
    float acc[4] = {0.f, 0.f, 0.f, 0.f};
    for (int k = 0; k < FI; ++k) {
        float w = W[k * FO + c];
        acc[0] += sh[(ty * 4 + 0) * FI + k] * w;
        acc[1] += sh[(ty * 4 + 1) * FI + k] * w;
        acc[2] += sh[(ty * 4 + 2) * FI + k] * w;
        acc[3] += sh[(ty * 4 + 3) * FI + k] * w;
    }
    __half hb[4];
    #pragma unroll
    for (int q = 0; q < 4; ++q) hb[q] = __float2half_rn(acc[q]);
    size_t off = (size_t)c * NN + row0 + ty * 4;
    *(uint2*)&g_WhT[off] = *(uint2*)hb;

    float a1 = a[c], a2 = a[FO + c];
    float s1[4], s2[4];
    #pragma unroll
    for (int q = 0; q < 4; ++q) { s1[q] = acc[q] * a1; s2[q] = acc[q] * a2; }
    #pragma unroll
    for (int o = 16; o > 0; o >>= 1)
        #pragma unroll
        for (int q = 0; q < 4; ++q) {
            s1[q] += __shfl_xor_sync(0xffffffffu, s1[q], o);
            s2[q] += __shfl_xor_sync(0xffffffffu, s2[q], o);
        }
    if ((threadIdx.x & 31) == 0) {
        int wp = (threadIdx.x >> 5) & 1;
        #pragma unroll
        for (int q = 0; q < 4; ++q) {
            sred[ty * 4 + q][wp][0] = s1[q];
            sred[ty * 4 + q][wp][1] = s2[q];
        }
    }
    __syncthreads();
    if (threadIdx.x < 16) {
        float f1 = (sred[threadIdx.x][0][0] + sred[threadIdx.x][1][0]) * LOG2E;
        float f2 = (sred[threadIdx.x][0][1] + sred[threadIdx.x][1][1]) * LOG2E;
        int row = row0 + threadIdx.x;
        g_e1p[row] = __floats2half2_rn(exp2f(f1), exp2f(0.2f * f1));
        g_e2h[row] = __float2half_rn(exp2f(f2));
        g_e2l[row] = __float2half_rn(exp2f(0.2f * f2));
    }
}

// profiling anchors: keep gat_mma in ncu's fixed capture slot
__global__ void prof_pad() {}

// -- Kernel 2: cp.async adj pipeline + fp16 P-gen + PRMT masks + mma.sync --
__global__ __launch_bounds__(256, 3) void gat_mma(const int* __restrict__ adj) {
    extern __shared__ char smem[];
    const unsigned sb = s2u(smem);
    uint4* sE2q = (uint4*)(smem + SM_E2Q);

    const int tid = threadIdx.x, wid = tid >> 5, lane = tid & 31;
    const int half = lane >> 4, seg = lane & 15;
    const int q = lane & 3, r0 = lane >> 2;
    const int mt = blockIdx.x, jq = blockIdx.y;
    const int i0 = mt * BM;
    const int m0 = wid * 16;

    // adj region owned by this thread: rows m0+2u+half, 16B at col seg*4
    const int rbase = i0 + m0 + half;
    const int* aptr = adj + (size_t)rbase * NN + seg * 4;
    const unsigned adst = sb + SM_ADJ + (m0 + half) * 256 + seg * 16;  // +u*512
    const char* ards = smem + SM_ADJ + (m0 + half) * 256 + seg * 16;

    // B-stage map
    const int bc = tid >> 2, bseg = tid & 3;

    // B fragment addressing (ldmatrix)
    const unsigned b_addr = sb + SM_B +
        ((lane & 7) + ((lane >> 4) & 1) * 8) * PSTB + ((lane >> 3) & 1) * 16;
    unsigned bd[2];
    bd[0] = bd[1] = (lane < 4) ? 0x3C003C00u : 0u;

    float acc[8][4], accD[4];
    #pragma unroll
    for (int nt = 0; nt < 8; ++nt)
        #pragma unroll
        for (int c = 0; c < 4; ++c) acc[nt][c] = 0.f;
    #pragma unroll
    for (int c = 0; c < 4; ++c) accD[c] = 0.f;

    const int rowA = i0 + m0 + r0;
    const int rowB = rowA + 8;
    const __half2 e1A = (rowA < NN) ? g_e1p[rowA] : __float2half2_rn(0.f);
    const __half2 e1B = (rowB < NN) ? g_e1p[rowB] : __float2half2_rn(0.f);
    const __half2 E0h = __half2half2(__low2half(e1A));
    const __half2 E0l = __half2half2(__high2half(e1A));
    const __half2 E1h = __half2half2(__low2half(e1B));
    const __half2 E1l = __half2half2(__high2half(e1B));

    const int uA = r0 >> 1;
    const unsigned sh = 16 * (r0 & 1) + (q >> 1);
    const bool qodd = (q & 1) != 0;

    // prologue: async-copy the first tile's adj
    {
        const int j0 = jq * BN;
        const bool jok = (j0 + seg * 4 + 3) < NN;
        #pragma unroll
        for (int u = 0; u < 8; ++u) {
            unsigned sz = (jok && (rbase + 2 * u < NN)) ? 16u : 0u;
            cp16(adst + u * 512, aptr + (size_t)(2 * u) * NN + j0, sz);
        }
        cp_commit();
    }
    __syncthreads();

    for (int t = jq; t < NT; t += NSPLIT) {
        const int j0 = t * BN;

        // ---- this tile's adj is resident: compress from smem ----
        cp_wait0();
        unsigned wA0 = 0, wA1 = 0, wB0 = 0, wB1 = 0;
        #pragma unroll
        for (int u = 0; u < 8; ++u) {
            int4 mm = *(const int4*)(ards + u * 512);
            unsigned t0 = __ballot_sync(0xffffffffu, mm.x != 0);
            unsigned t1 = __ballot_sync(0xffffffffu, mm.y != 0);
            unsigned t2 = __ballot_sync(0xffffffffu, mm.z != 0);
            unsigned t3 = __ballot_sync(0xffffffffu, mm.w != 0);
            unsigned s0w = qodd ? t2 : t0;
            unsigned s1w = qodd ? t3 : t1;
            if (u < 4) { if (u == uA) { wA0 = s0w; wA1 = s1w; } }
            else       { if (u == uA + 4) { wB0 = s0w; wB1 = s1w; } }
        }
        const unsigned RA =
            ((wA0 >> sh) & 0x55555555u) | (((wA1 >> sh) & 0x55555555u) << 1);
        const unsigned RB =
            ((wB0 >> sh) & 0x55555555u) | (((wB1 >> sh) & 0x55555555u) << 1);

        // ---- issue next tile's copies into the same (own) region ----
        {
            const int tn = t + NSPLIT;
            const int jn = tn * BN;
            const bool jokn = (tn < NT) && ((jn + seg * 4 + 3) < NN);
            #pragma unroll
            for (int u = 0; u < 8; ++u) {
                unsigned sz = (jokn && (rbase + 2 * u < NN)) ? 16u : 0u;
                cp16(adst + u * 512, aptr + (size_t)(2 * u) * NN + jn, sz);
            }
            cp_commit();
        }

        __syncthreads();   // previous tile's B/e2 reads complete

        // ---- stage B tile (WhT fp16) + repacked e2 table ----
        #pragma unroll
        for (int ch = 0; ch < 2; ++ch) {
            int e0 = bseg * 16 + ch * 8;
            uint4 v = make_uint4(0, 0, 0, 0);
            if (j0 + e0 + 7 < NN)
                v = *(const uint4*)(g_WhT + (size_t)bc * NN + j0 + e0);
            *(uint4*)(smem + SM_B + bc * PSTB + e0 * 2) = v;
        }
        if (tid < 16) {
            int ks = tid >> 2, qq = tid & 3;
            int j = j0 + 16 * ks + 2 * qq;
            uint4 v;
            v.x = ldh2g(g_e2h, j);
            v.y = ldh2g(g_e2l, j);
            v.z = ldh2g(g_e2h, j + 8);
            v.w = ldh2g(g_e2l, j + 8);
            sE2q[tid] = v;
        }
        __syncthreads();

        // ---- per k-step: packed-fp16 A-frags + PRMT masks, ldsm B, HMMA ----
        #pragma unroll
        for (int ks = 0; ks < 4; ++ks) {
            unsigned nA = RA >> (4 * ks), nB = RB >> (4 * ks);
            unsigned mAx = msk2(nA), mAy = msk2(nA >> 2);
            unsigned mBx = msk2(nB), mBy = msk2(nB >> 2);
            uint4 E = sE2q[ks * 4 + q];
            __half2 eh0 = *(__half2*)&E.x, el0 = *(__half2*)&E.y;
            __half2 eh8 = *(__half2*)&E.z, el8 = *(__half2*)&E.w;

            __half2 pA0 = __hmax2(__hmul2(E0h, eh0), __hmul2(E0l, el0));
            __half2 pB0 = __hmax2(__hmul2(E1h, eh0), __hmul2(E1l, el0));
            __half2 pA8 = __hmax2(__hmul2(E0h, eh8), __hmul2(E0l, el8));
            __half2 pB8 = __hmax2(__hmul2(E1h, eh8), __hmul2(E1l, el8));

            unsigned af[4];
            af[0] = (*(unsigned*)&pA0) & mAx;
            af[1] = (*(unsigned*)&pB0) & mBx;
            af[2] = (*(unsigned*)&pA8) & mAy;
            af[3] = (*(unsigned*)&pB8) & mBy;

            unsigned bfr[16];
            #pragma unroll
            for (int g = 0; g < 4; ++g)
                ldsm4(bfr + 4 * g, b_addr + g * 16 * PSTB + ks * 32);
            #pragma unroll
            for (int nt = 0; nt < 8; ++nt)
                hmma(acc[nt], af, bfr + nt * 2);
            hmma(accD, af, bd);
        }
    }
    cp_wait0();   // drain trailing group

    // ---- epilogue ----
    {
        float* pa = g_pacc + (size_t)(jq * RT + mt) * BM * FO;
        int row = m0 + r0;
        int col = q * 2;
        #pragma unroll
        for (int nt = 0; nt < 8; ++nt) {
            *(float2*)&pa[row * FO + nt * 8 + col] = make_float2(acc[nt][0], acc[nt][1]);
            *(float2*)&pa[(row + 8) * FO + nt * 8 + col] = make_float2(acc[nt][2], acc[nt][3]);
        }
    }
    if (q == 0) {
        float* pd = g_pden + (jq * RT + mt) * BM;
        int row = m0 + r0;
        pd[row] = accD[0];
        pd[row + 8] = accD[2];
    }
}

// ---------------- Kernel 3: combine partials + ELU ----------------
__global__ __launch_bounds__(256) void combine_kernel(float* __restrict__ out) {
    int idx = blockIdx.x * 256 + threadIdx.x;
    if (idx >= NN * FO) return;
    int i = idx >> 6, c = idx & 63;
    int mt = i >> 7, row = i & 127;
    float a = 0.f, d = 0.f;
    #pragma unroll
    for (int q = 0; q < NSPLIT; ++q) {
        a += g_pacc[(size_t)(q * RT + mt) * BM * FO + row * FO + c];
        d += g_pden[(q * RT + mt) * BM + row];
    }
    float v = a / d;
    out[idx] = v > 0.f ? v : expm1f(v);
}

extern "C" void kernel_launch(void* const* d_in, const int* in_sizes, int n_in,
                              void* d_out, int out_size) {
    const float* h   = (const float*)d_in[0];
    const int*   adj = (const int*)d_in[1];
    const float* W   = (const float*)d_in[2];
    const float* a   = (const float*)d_in[3];
    float* out = (float*)d_out;

    wh_kernel<<<NN / 16, 256>>>(h, W, a);
    prof_pad<<<1, 1>>>();
    prof_pad<<<1, 1>>>();   // keeps gat_mma in ncu's capture slot
    gat_mma<<<dim3(RT, NSPLIT), 256, SM_TOTAL>>>(adj);
    combine_kernel<<<(NN * FO + 255) / 256, 256>>>(out);
}